// round 12
// baseline (speedup 1.0000x reference)
#include <cuda_runtime.h>
#include <cuda_bf16.h>

#define BB     128
#define NTOK   1369
#define DINOD  384
#define CLIPD  512
#define NH     8
#define TILE   32
#define CHUNKS 43                 // ceil(1369/32)
#define BUFF   (TILE*DINOD)       // 12288 floats per buffer

// k3 smem layout (floats)
#define OFF_LG  (2*BUFF)              // 24576 : 32*8 logits
#define OFF_WSM (OFF_LG + TILE*NH)    // 24832 : 32*8 weights
#define OFF_RS  (OFF_WSM + TILE*NH)   // 25088 : 8 rescale
#define OFF_LS  (OFF_RS + 8)          // 25096 : 8 running l
#define SMEM3   ((OFF_LS + 8)*4)      // 100416 bytes

#define SMEM4   ((4*DINOD*NH + 64 + 64 + 8)*4)   // 49696 bytes

__device__ __align__(16) float g_Q[BB*CLIPD];
__device__ __align__(16) float g_qk[BB*NH*DINOD];
__device__ __align__(16) float g_ctx[BB*DINOD*NH];   // normalized ctx, layout [b][c][h]

// ---- packed f32x2 helpers ----
__device__ __forceinline__ unsigned long long pk2(float x, float y){
  unsigned long long r; asm("mov.b64 %0, {%1,%2};" : "=l"(r) : "f"(x), "f"(y)); return r;
}
__device__ __forceinline__ float2 upk2(unsigned long long v){
  float2 r; asm("mov.b64 {%0,%1}, %2;" : "=f"(r.x), "=f"(r.y) : "l"(v)); return r;
}
__device__ __forceinline__ void fma2(unsigned long long& d, unsigned long long a, unsigned long long b){
  asm("fma.rn.f32x2 %0, %1, %2, %0;" : "+l"(d) : "l"(a), "l"(b));
}
__device__ __forceinline__ void mul2(unsigned long long& d, unsigned long long a){
  asm("mul.rn.f32x2 %0, %0, %1;" : "+l"(d) : "l"(a));
}
__device__ __forceinline__ void cp16z(float* dst, const float* src, int sz){
  unsigned sa = (unsigned)__cvta_generic_to_shared(dst);
  asm volatile("cp.async.cg.shared.global [%0], [%1], 16, %2;" :: "r"(sa), "l"(src), "r"(sz) : "memory");
}

// ============ K1: Q = clip @ Wq + bq  (4 batches/CTA, grid 32) ============
__global__ void __launch_bounds__(256) k1_qproj(const float* __restrict__ clip,
                                                const float* __restrict__ Wq,
                                                const float* __restrict__ bq){
  __shared__ float cs[4][CLIPD];
  int t = threadIdx.x;
  int b0 = blockIdx.x * 4;
  for(int i = t; i < 4*CLIPD; i += 256)
    cs[i>>9][i&511] = clip[(size_t)b0*CLIPD + i];
  __syncthreads();
  int col = 2*t;
  float2 bq2 = *(const float2*)(bq + col);
  unsigned long long A0 = pk2(bq2.x, bq2.y), A1 = A0, A2 = A0, A3 = A0;
  #pragma unroll 8
  for(int c = 0; c < CLIPD; c++){
    float2 w = *(const float2*)(Wq + (size_t)c*CLIPD + col);
    unsigned long long wp = pk2(w.x, w.y);
    float c0 = cs[0][c], c1 = cs[1][c], c2 = cs[2][c], c3 = cs[3][c];
    fma2(A0, wp, pk2(c0, c0));
    fma2(A1, wp, pk2(c1, c1));
    fma2(A2, wp, pk2(c2, c2));
    fma2(A3, wp, pk2(c3, c3));
  }
  *(float2*)(g_Q + (size_t)(b0+0)*CLIPD + col) = upk2(A0);
  *(float2*)(g_Q + (size_t)(b0+1)*CLIPD + col) = upk2(A1);
  *(float2*)(g_Q + (size_t)(b0+2)*CLIPD + col) = upk2(A2);
  *(float2*)(g_Q + (size_t)(b0+3)*CLIPD + col) = upk2(A3);
}

// ============ K2: qk[b,h,c] = sum_d Wk[c,h*64+d]*Q[b,h*64+d]/(8*temp)  (2 b/CTA, grid 64) ============
__global__ void __launch_bounds__(512) k2_qk(const float* __restrict__ Wk,
                                             const float* __restrict__ temp){
  __shared__ float Qs[2][CLIPD];
  int t = threadIdx.x, wid = t>>5, lane = t&31;
  int b0 = blockIdx.x * 2;
  for(int i = t; i < 2*CLIPD; i += 512) Qs[i>>9][i&511] = g_Q[(size_t)b0*CLIPD + i];
  __syncthreads();
  float inv_scale = 1.0f/(8.0f*temp[0]);
  float4 qv[2][4];
  #pragma unroll
  for(int bb = 0; bb < 2; bb++)
    #pragma unroll
    for(int k = 0; k < 4; k++)
      qv[bb][k] = *(const float4*)(&Qs[bb][lane*4 + k*128]);
  int hb = lane >> 4;
  for(int c = wid; c < DINOD; c += 16){
    const float4* wr = (const float4*)(Wk + (size_t)c*CLIPD);
    float s[4][2];
    #pragma unroll
    for(int k = 0; k < 4; k++){
      float4 w4 = wr[lane + k*32];
      #pragma unroll
      for(int bb = 0; bb < 2; bb++)
        s[k][bb] = w4.x*qv[bb][k].x + w4.y*qv[bb][k].y + w4.z*qv[bb][k].z + w4.w*qv[bb][k].w;
    }
    #pragma unroll
    for(int o = 8; o; o >>= 1)
      #pragma unroll
      for(int k = 0; k < 4; k++)
        #pragma unroll
        for(int bb = 0; bb < 2; bb++)
          s[k][bb] += __shfl_xor_sync(0xffffffffu, s[k][bb], o);
    if((lane & 15) == 0){
      #pragma unroll
      for(int k = 0; k < 4; k++)
        #pragma unroll
        for(int bb = 0; bb < 2; bb++)
          g_qk[((size_t)(b0+bb)*NH + 2*k + hb)*DINOD + c] = s[k][bb]*inv_scale;
    }
  }
}

// async-load one 32-token chunk (zfill past NTOK)
__device__ __forceinline__ void load_chunk(float* dst, const float* dino_b, int tok0, int t){
  #pragma unroll
  for(int k = 0; k < 6; k++){
    int gi = t + k*512;              // 0..3071 float4s
    int row = gi / 96, c4 = gi - row*96;
    int tok = tok0 + row;
    cp16z(dst + row*DINOD + c4*4, dino_b + (size_t)tok*DINOD + c4*4, (tok < NTOK) ? 16 : 0);
  }
}

// ============ K3: fused streaming single-query attention ============
// grid 128 (one b per CTA), 512 thr, 1 CTA/SM.
// Phase A: warp = (token-row, head-half); qk held in REGISTERS (loaded from gmem once).
//   Lane map: hl=lane&15 owns c = hl*4 + j*64 (j=0..5); lane>>4 picks head pair in half.
//   Half-warps read identical dino addresses (broadcast, crossbar-free).
// Phase B: thread t<384 owns column t; ctx in 4 persistent f32x2 registers.
__global__ void __launch_bounds__(512, 1) k3_attn(const float* __restrict__ dino){
  extern __shared__ float sm[];
  int t = threadIdx.x, lane = t & 31, warp = t >> 5;
  int hh = warp & 1;                 // head half (0: heads 0-3, 1: heads 4-7)
  int trow = warp >> 1;              // token rows trow + 8k, k=0..3
  int hl = lane & 15;
  int h0 = hh*4 + (lane >> 4)*2;     // this lane's head pair
  int b = blockIdx.x;
  const float* dino_b = dino + (size_t)b*NTOK*DINOD;

  // qk -> registers (2 heads x 24 floats as f32x2 pairs)
  unsigned long long q0[6][2], q1[6][2];
  {
    const float* qkb = g_qk + ((size_t)b*NH + h0)*DINOD;
    #pragma unroll
    for(int j = 0; j < 6; j++){
      float4 v = *(const float4*)(qkb + j*64 + hl*4);
      q0[j][0] = pk2(v.x,v.y); q0[j][1] = pk2(v.z,v.w);
      float4 u = *(const float4*)(qkb + DINOD + j*64 + hl*4);
      q1[j][0] = pk2(u.x,u.y); q1[j][1] = pk2(u.z,u.w);
    }
  }

  load_chunk(sm, dino_b, 0, t);
  asm volatile("cp.async.commit_group;" ::: "memory");

  unsigned long long A0=0ull, A1=0ull, A2=0ull, A3=0ull;   // ctx col t, head pairs
  float m_run = -1e30f, l_run = 0.0f;                       // per-lane copy, warp<8

  for(int i = 0; i < CHUNKS; i++){
    asm volatile("cp.async.wait_group 0;" ::: "memory");
    __syncthreads();                       // chunk i ready + prev Phase B done
    if(i+1 < CHUNKS)
      load_chunk(sm + ((i+1)&1)*BUFF, dino_b, (i+1)*TILE, t);
    asm volatile("cp.async.commit_group;" ::: "memory");

    const float* dcur = sm + (i&1)*BUFF;
    int base = i*TILE;

    // ---- Phase A: warp handles 4 tokens x 4 heads ----
    #pragma unroll
    for(int k = 0; k < 4; k++){
      int tok = trow + 8*k;
      const float4* rf = (const float4*)(dcur + tok*DINOD);
      unsigned long long s0p = 0ull, s1p = 0ull;
      #pragma unroll
      for(int j = 0; j < 6; j++){
        float4 d = rf[j*16 + hl];
        unsigned long long dA = pk2(d.x,d.y), dB = pk2(d.z,d.w);
        fma2(s0p, dA, q0[j][0]); fma2(s0p, dB, q0[j][1]);
        fma2(s1p, dA, q1[j][0]); fma2(s1p, dB, q1[j][1]);
      }
      float2 P0 = upk2(s0p), P1 = upk2(s1p);
      float s0 = P0.x + P0.y, s1 = P1.x + P1.y;
      #pragma unroll
      for(int o = 8; o; o >>= 1){
        s0 += __shfl_xor_sync(0xffffffffu, s0, o);
        s1 += __shfl_xor_sync(0xffffffffu, s1, o);
      }
      if(hl == 0){
        bool valid = (base + tok < NTOK);
        *(float2*)(sm + OFF_LG + tok*NH + h0) =
            valid ? make_float2(s0, s1) : make_float2(-1e30f, -1e30f);
      }
    }
    __syncthreads();
    // ---- softmax bookkeeping: warp h (h<8) handles head h over 32 tokens ----
    if(warp < 8){
      float lgv = sm[OFF_LG + lane*NH + warp];
      float mx = lgv;
      #pragma unroll
      for(int o = 16; o; o >>= 1) mx = fmaxf(mx, __shfl_xor_sync(0xffffffffu, mx, o));
      float mn = fmaxf(m_run, mx);
      float r  = __expf(m_run - mn);
      m_run = mn;
      float wv = __expf(lgv - mn);
      float ls = wv;
      #pragma unroll
      for(int o = 16; o; o >>= 1) ls += __shfl_xor_sync(0xffffffffu, ls, o);
      l_run = l_run*r + ls;
      sm[OFF_WSM + lane*NH + warp] = wv;
      if(lane == 0){ sm[OFF_RS + warp] = r; sm[OFF_LS + warp] = l_run; }
    }
    __syncthreads();
    // ---- Phase B: ctx update in registers (thread = column) ----
    if(t < DINOD){
      ulonglong2 ra = *(const ulonglong2*)(sm + OFF_RS);
      ulonglong2 rb = *(const ulonglong2*)(sm + OFF_RS + 4);
      mul2(A0, ra.x); mul2(A1, ra.y); mul2(A2, rb.x); mul2(A3, rb.y);
      const float* dc = dcur + t;
      #pragma unroll 4
      for(int n = 0; n < TILE; n++){
        float dv = dc[n*DINOD];
        unsigned long long dd = pk2(dv, dv);
        ulonglong2 wa = *(const ulonglong2*)(sm + OFF_WSM + n*NH);
        ulonglong2 wb = *(const ulonglong2*)(sm + OFF_WSM + n*NH + 4);
        fma2(A0, wa.x, dd); fma2(A1, wa.y, dd);
        fma2(A2, wb.x, dd); fma2(A3, wb.y, dd);
      }
    }
  }

  // normalize and store ctx
  if(t < DINOD){
    float4 l0 = *(const float4*)(sm + OFF_LS);
    float4 l1 = *(const float4*)(sm + OFF_LS + 4);
    unsigned long long i01 = pk2(1.0f/l0.x, 1.0f/l0.y);
    unsigned long long i23 = pk2(1.0f/l0.z, 1.0f/l0.w);
    unsigned long long i45 = pk2(1.0f/l1.x, 1.0f/l1.y);
    unsigned long long i67 = pk2(1.0f/l1.z, 1.0f/l1.w);
    mul2(A0, i01); mul2(A1, i23); mul2(A2, i45); mul2(A3, i67);
    float2 p0 = upk2(A0), p1 = upk2(A1), p2 = upk2(A2), p3 = upk2(A3);
    float* dst = g_ctx + ((size_t)b*DINOD + t)*NH;
    ((float4*)dst)[0] = make_float4(p0.x, p0.y, p1.x, p1.y);
    ((float4*)dst)[1] = make_float4(p2.x, p2.y, p3.x, p3.y);
  }
}

// ============ K4: out = ctx @ Wv + bv, LayerNorm  (4 batches/CTA, grid 32) ============
__global__ void __launch_bounds__(512) k4_out(const float* __restrict__ Wv,
                                              const float* __restrict__ bv,
                                              const float* __restrict__ gamma,
                                              const float* __restrict__ beta,
                                              float* __restrict__ out){
  extern __shared__ float sm4[];
  float* cs   = sm4;                     // [4][DINOD*NH] ctx, layout [bb][c*8+h]
  float* redS = sm4 + 4*DINOD*NH;        // [4][16]
  float* redQ = redS + 64;               // [4][16]
  float* stats = redQ + 64;              // [8]: s[4], q[4]
  int t = threadIdx.x, wid = t>>5, lane = t&31;
  int b0 = blockIdx.x * 4;
  for(int i = t; i < 4*DINOD*NH; i += 512)
    cs[i] = g_ctx[(size_t)b0*DINOD*NH + i];
  __syncthreads();
  int h = t >> 6;
  float bvt = bv[t];
  float a0 = bvt, a1 = bvt, a2 = bvt, a3 = bvt;
  const float* c0p = cs + 0*DINOD*NH + h;
  const float* c1p = cs + 1*DINOD*NH + h;
  const float* c2p = cs + 2*DINOD*NH + h;
  const float* c3p = cs + 3*DINOD*NH + h;
  #pragma unroll 4
  for(int c = 0; c < DINOD; c++){
    float wv = Wv[(size_t)c*CLIPD + t];
    a0 = fmaf(c0p[c*NH], wv, a0);
    a1 = fmaf(c1p[c*NH], wv, a1);
    a2 = fmaf(c2p[c*NH], wv, a2);
    a3 = fmaf(c3p[c*NH], wv, a3);
  }
  float s0=a0, s1=a1, s2=a2, s3=a3;
  float q0=a0*a0, q1=a1*a1, q2=a2*a2, q3=a3*a3;
  #pragma unroll
  for(int o = 16; o; o >>= 1){
    s0 += __shfl_xor_sync(0xffffffffu, s0, o);
    s1 += __shfl_xor_sync(0xffffffffu, s1, o);
    s2 += __shfl_xor_sync(0xffffffffu, s2, o);
    s3 += __shfl_xor_sync(0xffffffffu, s3, o);
    q0 += __shfl_xor_sync(0xffffffffu, q0, o);
    q1 += __shfl_xor_sync(0xffffffffu, q1, o);
    q2 += __shfl_xor_sync(0xffffffffu, q2, o);
    q3 += __shfl_xor_sync(0xffffffffu, q3, o);
  }
  if(lane == 0){
    redS[0*16+wid]=s0; redS[1*16+wid]=s1; redS[2*16+wid]=s2; redS[3*16+wid]=s3;
    redQ[0*16+wid]=q0; redQ[1*16+wid]=q1; redQ[2*16+wid]=q2; redQ[3*16+wid]=q3;
  }
  __syncthreads();
  if(t < 8){
    int bb = t & 3;
    const float* src = (t < 4) ? (redS + bb*16) : (redQ + bb*16);
    float x = 0.0f;
    #pragma unroll
    for(int i = 0; i < 16; i++) x += src[i];
    stats[t] = x;
  }
  __syncthreads();
  float g = gamma[t], be = beta[t];
  #pragma unroll
  for(int bb = 0; bb < 4; bb++){
    float a = (bb==0)?a0:(bb==1)?a1:(bb==2)?a2:a3;
    float mu = stats[bb]*(1.0f/512.0f);
    float var = stats[4+bb]*(1.0f/512.0f) - mu*mu;
    float rstd = rsqrtf(var + 1e-5f);
    out[(size_t)(b0+bb)*CLIPD + t] = (a - mu)*rstd*g + be;
  }
}

extern "C" void kernel_launch(void* const* d_in, const int* in_sizes, int n_in,
                              void* d_out, int out_size) {
  const float* dino  = (const float*)d_in[0];
  const float* clip  = (const float*)d_in[1];
  const float* Wq    = (const float*)d_in[2];
  const float* bq    = (const float*)d_in[3];
  const float* Wk    = (const float*)d_in[4];
  // d_in[5] = bk: cancels in softmax
  const float* Wv    = (const float*)d_in[6];
  const float* bv    = (const float*)d_in[7];
  const float* temp  = (const float*)d_in[8];
  const float* gamma = (const float*)d_in[9];
  const float* beta  = (const float*)d_in[10];
  float* out = (float*)d_out;

  cudaFuncSetAttribute(k3_attn, cudaFuncAttributeMaxDynamicSharedMemorySize, SMEM3);
  cudaFuncSetAttribute(k4_out,  cudaFuncAttributeMaxDynamicSharedMemorySize, SMEM4);

  k1_qproj<<<32, 256>>>(clip, Wq, bq);
  k2_qk<<<64, 512>>>(Wk, temp);
  k3_attn<<<BB, 512, SMEM3>>>(dino);
  k4_out<<<32, 512, SMEM4>>>(Wv, bv, gamma, beta, out);
}

// round 13
// speedup vs baseline: 1.0004x; 1.0004x over previous
#include <cuda_runtime.h>
#include <cuda_bf16.h>

#define BB     128
#define NTOK   1369
#define DINOD  384
#define CLIPD  512
#define NH     8
#define TILE   32
#define CHUNKS 43                 // ceil(1369/32)
#define BUFF   (TILE*DINOD)       // 12288 floats per buffer

// k3 smem layout (floats)
#define OFF_LG  (2*BUFF)              // 24576 : 32*8 logits
#define OFF_WSM (OFF_LG + TILE*NH)    // 24832 : 32*8 weights
#define OFF_RS  (OFF_WSM + TILE*NH)   // 25088 : 8 rescale
#define OFF_LS  (OFF_RS + 8)          // 25096 : 8 running l
#define SMEM3   ((OFF_LS + 8)*4)      // 100416 bytes

#define SMEM4   ((4*DINOD*NH + 64 + 64 + 8)*4)   // 49696 bytes

__device__ __align__(16) float g_Q[BB*CLIPD];
__device__ __align__(16) float g_qk[BB*NH*DINOD];
__device__ __align__(16) float g_ctx[BB*DINOD*NH];   // normalized ctx, layout [b][c][h]

// ---- packed f32x2 helpers ----
__device__ __forceinline__ unsigned long long pk2(float x, float y){
  unsigned long long r; asm("mov.b64 %0, {%1,%2};" : "=l"(r) : "f"(x), "f"(y)); return r;
}
__device__ __forceinline__ float2 upk2(unsigned long long v){
  float2 r; asm("mov.b64 {%0,%1}, %2;" : "=f"(r.x), "=f"(r.y) : "l"(v)); return r;
}
__device__ __forceinline__ void fma2(unsigned long long& d, unsigned long long a, unsigned long long b){
  asm("fma.rn.f32x2 %0, %1, %2, %0;" : "+l"(d) : "l"(a), "l"(b));
}
__device__ __forceinline__ void mul2(unsigned long long& d, unsigned long long a){
  asm("mul.rn.f32x2 %0, %0, %1;" : "+l"(d) : "l"(a));
}
__device__ __forceinline__ void cp16z(float* dst, const float* src, int sz){
  unsigned sa = (unsigned)__cvta_generic_to_shared(dst);
  asm volatile("cp.async.cg.shared.global [%0], [%1], 16, %2;" :: "r"(sa), "l"(src), "r"(sz) : "memory");
}

// ============ K1: Q = clip @ Wq + bq  (4 batches/CTA, grid 32) ============
__global__ void __launch_bounds__(256) k1_qproj(const float* __restrict__ clip,
                                                const float* __restrict__ Wq,
                                                const float* __restrict__ bq){
  __shared__ float cs[4][CLIPD];
  int t = threadIdx.x;
  int b0 = blockIdx.x * 4;
  for(int i = t; i < 4*CLIPD; i += 256)
    cs[i>>9][i&511] = clip[(size_t)b0*CLIPD + i];
  __syncthreads();
  int col = 2*t;
  float2 bq2 = *(const float2*)(bq + col);
  unsigned long long A0 = pk2(bq2.x, bq2.y), A1 = A0, A2 = A0, A3 = A0;
  #pragma unroll 8
  for(int c = 0; c < CLIPD; c++){
    float2 w = *(const float2*)(Wq + (size_t)c*CLIPD + col);
    unsigned long long wp = pk2(w.x, w.y);
    float c0 = cs[0][c], c1 = cs[1][c], c2 = cs[2][c], c3 = cs[3][c];
    fma2(A0, wp, pk2(c0, c0));
    fma2(A1, wp, pk2(c1, c1));
    fma2(A2, wp, pk2(c2, c2));
    fma2(A3, wp, pk2(c3, c3));
  }
  *(float2*)(g_Q + (size_t)(b0+0)*CLIPD + col) = upk2(A0);
  *(float2*)(g_Q + (size_t)(b0+1)*CLIPD + col) = upk2(A1);
  *(float2*)(g_Q + (size_t)(b0+2)*CLIPD + col) = upk2(A2);
  *(float2*)(g_Q + (size_t)(b0+3)*CLIPD + col) = upk2(A3);
}

// ============ K2: qk[b,h,c] = sum_d Wk[c,h*64+d]*Q[b,h*64+d]/(8*temp)  (2 b/CTA, grid 64) ============
__global__ void __launch_bounds__(512) k2_qk(const float* __restrict__ Wk,
                                             const float* __restrict__ temp){
  __shared__ float Qs[2][CLIPD];
  int t = threadIdx.x, wid = t>>5, lane = t&31;
  int b0 = blockIdx.x * 2;
  for(int i = t; i < 2*CLIPD; i += 512) Qs[i>>9][i&511] = g_Q[(size_t)b0*CLIPD + i];
  __syncthreads();
  float inv_scale = 1.0f/(8.0f*temp[0]);
  float4 qv[2][4];
  #pragma unroll
  for(int bb = 0; bb < 2; bb++)
    #pragma unroll
    for(int k = 0; k < 4; k++)
      qv[bb][k] = *(const float4*)(&Qs[bb][lane*4 + k*128]);
  int hb = lane >> 4;
  for(int c = wid; c < DINOD; c += 16){
    const float4* wr = (const float4*)(Wk + (size_t)c*CLIPD);
    float s[4][2];
    #pragma unroll
    for(int k = 0; k < 4; k++){
      float4 w4 = wr[lane + k*32];
      #pragma unroll
      for(int bb = 0; bb < 2; bb++)
        s[k][bb] = w4.x*qv[bb][k].x + w4.y*qv[bb][k].y + w4.z*qv[bb][k].z + w4.w*qv[bb][k].w;
    }
    #pragma unroll
    for(int o = 8; o; o >>= 1)
      #pragma unroll
      for(int k = 0; k < 4; k++)
        #pragma unroll
        for(int bb = 0; bb < 2; bb++)
          s[k][bb] += __shfl_xor_sync(0xffffffffu, s[k][bb], o);
    if((lane & 15) == 0){
      #pragma unroll
      for(int k = 0; k < 4; k++)
        #pragma unroll
        for(int bb = 0; bb < 2; bb++)
          g_qk[((size_t)(b0+bb)*NH + 2*k + hb)*DINOD + c] = s[k][bb]*inv_scale;
    }
  }
}

// async-load one 32-token chunk (zfill past NTOK)
__device__ __forceinline__ void load_chunk(float* dst, const float* dino_b, int tok0, int t){
  #pragma unroll
  for(int k = 0; k < 6; k++){
    int gi = t + k*512;              // 0..3071 float4s
    int row = gi / 96, c4 = gi - row*96;
    int tok = tok0 + row;
    cp16z(dst + row*DINOD + c4*4, dino_b + (size_t)tok*DINOD + c4*4, (tok < NTOK) ? 16 : 0);
  }
}

// ============ K3: fused streaming single-query attention ============
// grid 128 (one b per CTA), 512 thr, 1 CTA/SM.
// Phase A: warp = (token-row, head-half); qk held in REGISTERS (loaded from gmem once).
//   Lane map: hl=lane&15 owns c = hl*4 + j*64 (j=0..5); lane>>4 picks head pair in half.
//   Half-warps read identical dino addresses (broadcast, crossbar-free).
// Phase B: thread t<384 owns column t; ctx in 4 persistent f32x2 registers.
__global__ void __launch_bounds__(512, 1) k3_attn(const float* __restrict__ dino){
  extern __shared__ float sm[];
  int t = threadIdx.x, lane = t & 31, warp = t >> 5;
  int hh = warp & 1;                 // head half (0: heads 0-3, 1: heads 4-7)
  int trow = warp >> 1;              // token rows trow + 8k, k=0..3
  int hl = lane & 15;
  int h0 = hh*4 + (lane >> 4)*2;     // this lane's head pair
  int b = blockIdx.x;
  const float* dino_b = dino + (size_t)b*NTOK*DINOD;

  // qk -> registers (2 heads x 24 floats as f32x2 pairs)
  unsigned long long q0[6][2], q1[6][2];
  {
    const float* qkb = g_qk + ((size_t)b*NH + h0)*DINOD;
    #pragma unroll
    for(int j = 0; j < 6; j++){
      float4 v = *(const float4*)(qkb + j*64 + hl*4);
      q0[j][0] = pk2(v.x,v.y); q0[j][1] = pk2(v.z,v.w);
      float4 u = *(const float4*)(qkb + DINOD + j*64 + hl*4);
      q1[j][0] = pk2(u.x,u.y); q1[j][1] = pk2(u.z,u.w);
    }
  }

  load_chunk(sm, dino_b, 0, t);
  asm volatile("cp.async.commit_group;" ::: "memory");

  unsigned long long A0=0ull, A1=0ull, A2=0ull, A3=0ull;   // ctx col t, head pairs
  float m_run = -1e30f, l_run = 0.0f;                       // per-lane copy, warp<8

  for(int i = 0; i < CHUNKS; i++){
    asm volatile("cp.async.wait_group 0;" ::: "memory");
    __syncthreads();                       // chunk i ready + prev Phase B done
    if(i+1 < CHUNKS)
      load_chunk(sm + ((i+1)&1)*BUFF, dino_b, (i+1)*TILE, t);
    asm volatile("cp.async.commit_group;" ::: "memory");

    const float* dcur = sm + (i&1)*BUFF;
    int base = i*TILE;

    // ---- Phase A: warp handles 4 tokens x 4 heads ----
    #pragma unroll
    for(int k = 0; k < 4; k++){
      int tok = trow + 8*k;
      const float4* rf = (const float4*)(dcur + tok*DINOD);
      unsigned long long s0p = 0ull, s1p = 0ull;
      #pragma unroll
      for(int j = 0; j < 6; j++){
        float4 d = rf[j*16 + hl];
        unsigned long long dA = pk2(d.x,d.y), dB = pk2(d.z,d.w);
        fma2(s0p, dA, q0[j][0]); fma2(s0p, dB, q0[j][1]);
        fma2(s1p, dA, q1[j][0]); fma2(s1p, dB, q1[j][1]);
      }
      float2 P0 = upk2(s0p), P1 = upk2(s1p);
      float s0 = P0.x + P0.y, s1 = P1.x + P1.y;
      #pragma unroll
      for(int o = 8; o; o >>= 1){
        s0 += __shfl_xor_sync(0xffffffffu, s0, o);
        s1 += __shfl_xor_sync(0xffffffffu, s1, o);
      }
      if(hl == 0){
        bool valid = (base + tok < NTOK);
        *(float2*)(sm + OFF_LG + tok*NH + h0) =
            valid ? make_float2(s0, s1) : make_float2(-1e30f, -1e30f);
      }
    }
    __syncthreads();
    // ---- softmax bookkeeping: warp h (h<8) handles head h over 32 tokens ----
    if(warp < 8){
      float lgv = sm[OFF_LG + lane*NH + warp];
      float mx = lgv;
      #pragma unroll
      for(int o = 16; o; o >>= 1) mx = fmaxf(mx, __shfl_xor_sync(0xffffffffu, mx, o));
      float mn = fmaxf(m_run, mx);
      float r  = __expf(m_run - mn);
      m_run = mn;
      float wv = __expf(lgv - mn);
      float ls = wv;
      #pragma unroll
      for(int o = 16; o; o >>= 1) ls += __shfl_xor_sync(0xffffffffu, ls, o);
      l_run = l_run*r + ls;
      sm[OFF_WSM + lane*NH + warp] = wv;
      if(lane == 0){ sm[OFF_RS + warp] = r; sm[OFF_LS + warp] = l_run; }
    }
    __syncthreads();
    // ---- Phase B: ctx update in registers (thread = column) ----
    if(t < DINOD){
      ulonglong2 ra = *(const ulonglong2*)(sm + OFF_RS);
      ulonglong2 rb = *(const ulonglong2*)(sm + OFF_RS + 4);
      mul2(A0, ra.x); mul2(A1, ra.y); mul2(A2, rb.x); mul2(A3, rb.y);
      const float* dc = dcur + t;
      #pragma unroll 4
      for(int n = 0; n < TILE; n++){
        float dv = dc[n*DINOD];
        unsigned long long dd = pk2(dv, dv);
        ulonglong2 wa = *(const ulonglong2*)(sm + OFF_WSM + n*NH);
        ulonglong2 wb = *(const ulonglong2*)(sm + OFF_WSM + n*NH + 4);
        fma2(A0, wa.x, dd); fma2(A1, wa.y, dd);
        fma2(A2, wb.x, dd); fma2(A3, wb.y, dd);
      }
    }
  }

  // normalize and store ctx
  if(t < DINOD){
    float4 l0 = *(const float4*)(sm + OFF_LS);
    float4 l1 = *(const float4*)(sm + OFF_LS + 4);
    unsigned long long i01 = pk2(1.0f/l0.x, 1.0f/l0.y);
    unsigned long long i23 = pk2(1.0f/l0.z, 1.0f/l0.w);
    unsigned long long i45 = pk2(1.0f/l1.x, 1.0f/l1.y);
    unsigned long long i67 = pk2(1.0f/l1.z, 1.0f/l1.w);
    mul2(A0, i01); mul2(A1, i23); mul2(A2, i45); mul2(A3, i67);
    float2 p0 = upk2(A0), p1 = upk2(A1), p2 = upk2(A2), p3 = upk2(A3);
    float* dst = g_ctx + ((size_t)b*DINOD + t)*NH;
    ((float4*)dst)[0] = make_float4(p0.x, p0.y, p1.x, p1.y);
    ((float4*)dst)[1] = make_float4(p2.x, p2.y, p3.x, p3.y);
  }
}

// ============ K4: out = ctx @ Wv + bv, LayerNorm  (4 batches/CTA, grid 32) ============
__global__ void __launch_bounds__(512) k4_out(const float* __restrict__ Wv,
                                              const float* __restrict__ bv,
                                              const float* __restrict__ gamma,
                                              const float* __restrict__ beta,
                                              float* __restrict__ out){
  extern __shared__ float sm4[];
  float* cs   = sm4;                     // [4][DINOD*NH] ctx, layout [bb][c*8+h]
  float* redS = sm4 + 4*DINOD*NH;        // [4][16]
  float* redQ = redS + 64;               // [4][16]
  float* stats = redQ + 64;              // [8]: s[4], q[4]
  int t = threadIdx.x, wid = t>>5, lane = t&31;
  int b0 = blockIdx.x * 4;
  for(int i = t; i < 4*DINOD*NH; i += 512)
    cs[i] = g_ctx[(size_t)b0*DINOD*NH + i];
  __syncthreads();
  int h = t >> 6;
  float bvt = bv[t];
  float a0 = bvt, a1 = bvt, a2 = bvt, a3 = bvt;
  const float* c0p = cs + 0*DINOD*NH + h;
  const float* c1p = cs + 1*DINOD*NH + h;
  const float* c2p = cs + 2*DINOD*NH + h;
  const float* c3p = cs + 3*DINOD*NH + h;
  #pragma unroll 4
  for(int c = 0; c < DINOD; c++){
    float wv = Wv[(size_t)c*CLIPD + t];
    a0 = fmaf(c0p[c*NH], wv, a0);
    a1 = fmaf(c1p[c*NH], wv, a1);
    a2 = fmaf(c2p[c*NH], wv, a2);
    a3 = fmaf(c3p[c*NH], wv, a3);
  }
  float s0=a0, s1=a1, s2=a2, s3=a3;
  float q0=a0*a0, q1=a1*a1, q2=a2*a2, q3=a3*a3;
  #pragma unroll
  for(int o = 16; o; o >>= 1){
    s0 += __shfl_xor_sync(0xffffffffu, s0, o);
    s1 += __shfl_xor_sync(0xffffffffu, s1, o);
    s2 += __shfl_xor_sync(0xffffffffu, s2, o);
    s3 += __shfl_xor_sync(0xffffffffu, s3, o);
    q0 += __shfl_xor_sync(0xffffffffu, q0, o);
    q1 += __shfl_xor_sync(0xffffffffu, q1, o);
    q2 += __shfl_xor_sync(0xffffffffu, q2, o);
    q3 += __shfl_xor_sync(0xffffffffu, q3, o);
  }
  if(lane == 0){
    redS[0*16+wid]=s0; redS[1*16+wid]=s1; redS[2*16+wid]=s2; redS[3*16+wid]=s3;
    redQ[0*16+wid]=q0; redQ[1*16+wid]=q1; redQ[2*16+wid]=q2; redQ[3*16+wid]=q3;
  }
  __syncthreads();
  if(t < 8){
    int bb = t & 3;
    const float* src = (t < 4) ? (redS + bb*16) : (redQ + bb*16);
    float x = 0.0f;
    #pragma unroll
    for(int i = 0; i < 16; i++) x += src[i];
    stats[t] = x;
  }
  __syncthreads();
  float g = gamma[t], be = beta[t];
  #pragma unroll
  for(int bb = 0; bb < 4; bb++){
    float a = (bb==0)?a0:(bb==1)?a1:(bb==2)?a2:a3;
    float mu = stats[bb]*(1.0f/512.0f);
    float var = stats[4+bb]*(1.0f/512.0f) - mu*mu;
    float rstd = rsqrtf(var + 1e-5f);
    out[(size_t)(b0+bb)*CLIPD + t] = (a - mu)*rstd*g + be;
  }
}

extern "C" void kernel_launch(void* const* d_in, const int* in_sizes, int n_in,
                              void* d_out, int out_size) {
  const float* dino  = (const float*)d_in[0];
  const float* clip  = (const float*)d_in[1];
  const float* Wq    = (const float*)d_in[2];
  const float* bq    = (const float*)d_in[3];
  const float* Wk    = (const float*)d_in[4];
  // d_in[5] = bk: cancels in softmax
  const float* Wv    = (const float*)d_in[6];
  const float* bv    = (const float*)d_in[7];
  const float* temp  = (const float*)d_in[8];
  const float* gamma = (const float*)d_in[9];
  const float* beta  = (const float*)d_in[10];
  float* out = (float*)d_out;

  cudaFuncSetAttribute(k3_attn, cudaFuncAttributeMaxDynamicSharedMemorySize, SMEM3);
  cudaFuncSetAttribute(k4_out,  cudaFuncAttributeMaxDynamicSharedMemorySize, SMEM4);

  k1_qproj<<<32, 256>>>(clip, Wq, bq);
  k2_qk<<<64, 512>>>(Wk, temp);
  k3_attn<<<BB, 512, SMEM3>>>(dino);
  k4_out<<<32, 512, SMEM4>>>(Wv, bv, gamma, beta, out);
}

// round 14
// speedup vs baseline: 1.1457x; 1.1453x over previous
#include <cuda_runtime.h>
#include <cuda_bf16.h>

#define BB     128
#define NTOK   1369
#define DINOD  384
#define CLIPD  512
#define NH     8
#define TILE   32
#define CHUNKS 43                 // ceil(1369/32)
#define BUFF   (TILE*DINOD)       // 12288 floats per buffer

// k3 smem layout (floats)
#define OFF_LG  (2*BUFF)              // 24576 : 32*8 logits
#define OFF_WSM (OFF_LG + TILE*NH)    // 24832 : 32*8 weights
#define OFF_RS  (OFF_WSM + TILE*NH)   // 25088 : 8 rescale
#define OFF_LS  (OFF_RS + 8)          // 25096 : 8 running l
#define SMEM3   ((OFF_LS + 8)*4)      // 100448 bytes

__device__ __align__(16) float g_Q[BB*CLIPD];
__device__ __align__(16) float g_qk[BB*NH*DINOD];
__device__ __align__(16) float g_ctx[BB*DINOD*NH];   // normalized ctx, layout [b][c][h]

// ---- packed f32x2 helpers ----
__device__ __forceinline__ unsigned long long pk2(float x, float y){
  unsigned long long r; asm("mov.b64 %0, {%1,%2};" : "=l"(r) : "f"(x), "f"(y)); return r;
}
__device__ __forceinline__ float2 upk2(unsigned long long v){
  float2 r; asm("mov.b64 {%0,%1}, %2;" : "=f"(r.x), "=f"(r.y) : "l"(v)); return r;
}
__device__ __forceinline__ void fma2(unsigned long long& d, unsigned long long a, unsigned long long b){
  asm("fma.rn.f32x2 %0, %1, %2, %0;" : "+l"(d) : "l"(a), "l"(b));
}
__device__ __forceinline__ void mul2(unsigned long long& d, unsigned long long a){
  asm("mul.rn.f32x2 %0, %0, %1;" : "+l"(d) : "l"(a));
}
__device__ __forceinline__ void cp16z(float* dst, const float* src, int sz){
  unsigned sa = (unsigned)__cvta_generic_to_shared(dst);
  asm volatile("cp.async.cg.shared.global [%0], [%1], 16, %2;" :: "r"(sa), "l"(src), "r"(sz) : "memory");
}

// ============ K1: Q = clip @ Wq + bq  (grid 128 = 64 b-pairs x 2 col-halves) ============
__global__ void __launch_bounds__(128) k1_qproj(const float* __restrict__ clip,
                                                const float* __restrict__ Wq,
                                                const float* __restrict__ bq){
  __shared__ float cs[2][CLIPD];
  int t = threadIdx.x;
  int p = blockIdx.x >> 1, half = blockIdx.x & 1;
  int b0 = 2*p, b1 = 2*p + 1;
  for(int i = t; i < CLIPD; i += 128){
    cs[0][i] = clip[(size_t)b0*CLIPD + i];
    cs[1][i] = clip[(size_t)b1*CLIPD + i];
  }
  __syncthreads();
  int col = half*256 + 2*t;
  float2 bq2 = *(const float2*)(bq + col);
  unsigned long long A0 = pk2(bq2.x, bq2.y), A1 = A0;
  #pragma unroll 8
  for(int c = 0; c < CLIPD; c++){
    float2 w = *(const float2*)(Wq + (size_t)c*CLIPD + col);
    unsigned long long wp = pk2(w.x, w.y);
    float c0 = cs[0][c], c1 = cs[1][c];
    fma2(A0, wp, pk2(c0, c0));
    fma2(A1, wp, pk2(c1, c1));
  }
  *(float2*)(g_Q + (size_t)b0*CLIPD + col) = upk2(A0);
  *(float2*)(g_Q + (size_t)b1*CLIPD + col) = upk2(A1);
}

// ============ K2: qk[b,h,c] = sum_d Wk[c,h*64+d]*Q[b,h*64+d] / (8*temp)  (grid 128) ============
__global__ void __launch_bounds__(256) k2_qk(const float* __restrict__ Wk,
                                             const float* __restrict__ temp){
  __shared__ float Qs[CLIPD];
  int t = threadIdx.x, wid = t>>5, lane = t&31;
  int b = blockIdx.x;
  for(int i = t; i < CLIPD; i += 256) Qs[i] = g_Q[(size_t)b*CLIPD + i];
  __syncthreads();
  float inv_scale = 1.0f/(8.0f*temp[0]);
  float q4x[4], q4y[4], q4z[4], q4w[4];
  #pragma unroll
  for(int k = 0; k < 4; k++){
    float4 q = *(const float4*)(Qs + lane*4 + k*128);
    q4x[k]=q.x; q4y[k]=q.y; q4z[k]=q.z; q4w[k]=q.w;
  }
  int hb = lane >> 4;
  for(int c = wid; c < DINOD; c += 8){
    const float4* wr = (const float4*)(Wk + (size_t)c*CLIPD);
    float s[4];
    #pragma unroll
    for(int k = 0; k < 4; k++){
      float4 w4 = wr[lane + k*32];
      s[k] = w4.x*q4x[k] + w4.y*q4y[k] + w4.z*q4z[k] + w4.w*q4w[k];
    }
    #pragma unroll
    for(int o = 8; o; o >>= 1){
      #pragma unroll
      for(int k = 0; k < 4; k++) s[k] += __shfl_xor_sync(0xffffffffu, s[k], o);
    }
    if((lane & 15) == 0){
      #pragma unroll
      for(int k = 0; k < 4; k++)
        g_qk[((size_t)b*NH + 2*k + hb)*DINOD + c] = s[k]*inv_scale;
    }
  }
}

// async-load one 32-token chunk (zfill past NTOK)
__device__ __forceinline__ void load_chunk(float* dst, const float* dino_b, int tok0, int t){
  #pragma unroll
  for(int k = 0; k < 6; k++){
    int gi = t + k*512;              // 0..3071 float4s
    int row = gi / 96, c4 = gi - row*96;
    int tok = tok0 + row;
    cp16z(dst + row*DINOD + c4*4, dino_b + (size_t)tok*DINOD + c4*4, (tok < NTOK) ? 16 : 0);
  }
}

// ============ K3: fused streaming single-query attention (R13 version, kept) ============
// grid 128 (one b per CTA), 512 thr, 1 CTA/SM.
// Phase A: warp = (token-row, head-half); qk held in REGISTERS (loaded from gmem once).
// Phase B: thread t<384 owns column t; ctx in 4 persistent f32x2 registers.
__global__ void __launch_bounds__(512, 1) k3_attn(const float* __restrict__ dino){
  extern __shared__ float sm[];
  int t = threadIdx.x, lane = t & 31, warp = t >> 5;
  int hh = warp & 1;                 // head half
  int trow = warp >> 1;              // token rows trow + 8k
  int hl = lane & 15;
  int h0 = hh*4 + (lane >> 4)*2;     // this lane's head pair
  int b = blockIdx.x;
  const float* dino_b = dino + (size_t)b*NTOK*DINOD;

  // qk -> registers (2 heads x 24 floats as f32x2 pairs)
  unsigned long long q0[6][2], q1[6][2];
  {
    const float* qkb = g_qk + ((size_t)b*NH + h0)*DINOD;
    #pragma unroll
    for(int j = 0; j < 6; j++){
      float4 v = *(const float4*)(qkb + j*64 + hl*4);
      q0[j][0] = pk2(v.x,v.y); q0[j][1] = pk2(v.z,v.w);
      float4 u = *(const float4*)(qkb + DINOD + j*64 + hl*4);
      q1[j][0] = pk2(u.x,u.y); q1[j][1] = pk2(u.z,u.w);
    }
  }

  load_chunk(sm, dino_b, 0, t);
  asm volatile("cp.async.commit_group;" ::: "memory");

  unsigned long long A0=0ull, A1=0ull, A2=0ull, A3=0ull;   // ctx col t, head pairs
  float m_run = -1e30f, l_run = 0.0f;                       // per-lane copy, warp<8

  for(int i = 0; i < CHUNKS; i++){
    asm volatile("cp.async.wait_group 0;" ::: "memory");
    __syncthreads();                       // chunk i ready + prev Phase B done
    if(i+1 < CHUNKS)
      load_chunk(sm + ((i+1)&1)*BUFF, dino_b, (i+1)*TILE, t);
    asm volatile("cp.async.commit_group;" ::: "memory");

    const float* dcur = sm + (i&1)*BUFF;
    int base = i*TILE;

    // ---- Phase A: warp handles 4 tokens x 4 heads ----
    #pragma unroll
    for(int k = 0; k < 4; k++){
      int tok = trow + 8*k;
      const float4* rf = (const float4*)(dcur + tok*DINOD);
      unsigned long long s0p = 0ull, s1p = 0ull;
      #pragma unroll
      for(int j = 0; j < 6; j++){
        float4 d = rf[j*16 + hl];
        unsigned long long dA = pk2(d.x,d.y), dB = pk2(d.z,d.w);
        fma2(s0p, dA, q0[j][0]); fma2(s0p, dB, q0[j][1]);
        fma2(s1p, dA, q1[j][0]); fma2(s1p, dB, q1[j][1]);
      }
      float2 P0 = upk2(s0p), P1 = upk2(s1p);
      float s0 = P0.x + P0.y, s1 = P1.x + P1.y;
      #pragma unroll
      for(int o = 8; o; o >>= 1){
        s0 += __shfl_xor_sync(0xffffffffu, s0, o);
        s1 += __shfl_xor_sync(0xffffffffu, s1, o);
      }
      if(hl == 0){
        bool valid = (base + tok < NTOK);
        *(float2*)(sm + OFF_LG + tok*NH + h0) =
            valid ? make_float2(s0, s1) : make_float2(-1e30f, -1e30f);
      }
    }
    __syncthreads();
    // ---- softmax bookkeeping: warp h (h<8) handles head h over 32 tokens ----
    if(warp < 8){
      float lgv = sm[OFF_LG + lane*NH + warp];
      float mx = lgv;
      #pragma unroll
      for(int o = 16; o; o >>= 1) mx = fmaxf(mx, __shfl_xor_sync(0xffffffffu, mx, o));
      float mn = fmaxf(m_run, mx);
      float r  = __expf(m_run - mn);
      m_run = mn;
      float wv = __expf(lgv - mn);
      float ls = wv;
      #pragma unroll
      for(int o = 16; o; o >>= 1) ls += __shfl_xor_sync(0xffffffffu, ls, o);
      l_run = l_run*r + ls;
      sm[OFF_WSM + lane*NH + warp] = wv;
      if(lane == 0){ sm[OFF_RS + warp] = r; sm[OFF_LS + warp] = l_run; }
    }
    __syncthreads();
    // ---- Phase B: ctx update in registers (thread = column) ----
    if(t < DINOD){
      ulonglong2 ra = *(const ulonglong2*)(sm + OFF_RS);
      ulonglong2 rb = *(const ulonglong2*)(sm + OFF_RS + 4);
      mul2(A0, ra.x); mul2(A1, ra.y); mul2(A2, rb.x); mul2(A3, rb.y);
      const float* dc = dcur + t;
      #pragma unroll 4
      for(int n = 0; n < TILE; n++){
        float dv = dc[n*DINOD];
        unsigned long long dd = pk2(dv, dv);
        ulonglong2 wa = *(const ulonglong2*)(sm + OFF_WSM + n*NH);
        ulonglong2 wb = *(const ulonglong2*)(sm + OFF_WSM + n*NH + 4);
        fma2(A0, wa.x, dd); fma2(A1, wa.y, dd);
        fma2(A2, wb.x, dd); fma2(A3, wb.y, dd);
      }
    }
  }

  // normalize and store ctx
  if(t < DINOD){
    float4 l0 = *(const float4*)(sm + OFF_LS);
    float4 l1 = *(const float4*)(sm + OFF_LS + 4);
    unsigned long long i01 = pk2(1.0f/l0.x, 1.0f/l0.y);
    unsigned long long i23 = pk2(1.0f/l0.z, 1.0f/l0.w);
    unsigned long long i45 = pk2(1.0f/l1.x, 1.0f/l1.y);
    unsigned long long i67 = pk2(1.0f/l1.z, 1.0f/l1.w);
    mul2(A0, i01); mul2(A1, i23); mul2(A2, i45); mul2(A3, i67);
    float2 p0 = upk2(A0), p1 = upk2(A1), p2 = upk2(A2), p3 = upk2(A3);
    float* dst = g_ctx + ((size_t)b*DINOD + t)*NH;
    ((float4*)dst)[0] = make_float4(p0.x, p0.y, p1.x, p1.y);
    ((float4*)dst)[1] = make_float4(p2.x, p2.y, p3.x, p3.y);
  }
}

// ============ K4: out = ctx @ Wv + bv, LayerNorm  (R11 version: grid 128, 1024 thr) ============
__global__ void __launch_bounds__(1024) k4_out(const float* __restrict__ Wv,
                                               const float* __restrict__ bv,
                                               const float* __restrict__ gamma,
                                               const float* __restrict__ beta,
                                               float* __restrict__ out){
  __shared__ float cs[DINOD*NH];   // ctx, layout [c][h]
  __shared__ float red2[CLIPD];
  __shared__ float redS[16], redQ[16];
  __shared__ float stats[2];
  int t = threadIdx.x;
  int b = blockIdx.x;
  for(int i = t; i < DINOD*NH; i += 1024)
    cs[i] = g_ctx[(size_t)b*DINOD*NH + i];
  __syncthreads();
  int cg = t >> 9, col = t & 511, h = col >> 6;
  float acc = cg ? 0.0f : bv[col];
  {
    int c0 = cg*192;
    const float* wp = Wv + (size_t)c0*CLIPD + col;
    const float* cp = cs + c0*NH + h;
    #pragma unroll 8
    for(int c = 0; c < 192; c++)
      acc = fmaf(cp[c*NH], wp[(size_t)c*CLIPD], acc);
  }
  if(cg) red2[col] = acc;
  __syncthreads();
  float a = 0.0f;
  if(!cg){
    a = acc + red2[col];
    float s = a, q = a*a;
    #pragma unroll
    for(int o = 16; o; o >>= 1){
      s += __shfl_xor_sync(0xffffffffu, s, o);
      q += __shfl_xor_sync(0xffffffffu, q, o);
    }
    if((t&31) == 0){ redS[t>>5] = s; redQ[t>>5] = q; }
  }
  __syncthreads();
  if(t < 32){
    float v = (t < 16) ? redS[t] : redQ[t-16];
    #pragma unroll
    for(int o = 8; o; o >>= 1) v += __shfl_xor_sync(0xffffffffu, v, o);
    if(t == 0)  stats[0] = v;
    if(t == 16) stats[1] = v;
  }
  __syncthreads();
  if(!cg){
    float mu = stats[0]*(1.0f/512.0f);
    float var = stats[1]*(1.0f/512.0f) - mu*mu;
    float rstd = rsqrtf(var + 1e-5f);
    out[(size_t)b*CLIPD + col] = (a - mu)*rstd*gamma[col] + beta[col];
  }
}

extern "C" void kernel_launch(void* const* d_in, const int* in_sizes, int n_in,
                              void* d_out, int out_size) {
  const float* dino  = (const float*)d_in[0];
  const float* clip  = (const float*)d_in[1];
  const float* Wq    = (const float*)d_in[2];
  const float* bq    = (const float*)d_in[3];
  const float* Wk    = (const float*)d_in[4];
  // d_in[5] = bk: cancels in softmax
  const float* Wv    = (const float*)d_in[6];
  const float* bv    = (const float*)d_in[7];
  const float* temp  = (const float*)d_in[8];
  const float* gamma = (const float*)d_in[9];
  const float* beta  = (const float*)d_in[10];
  float* out = (float*)d_out;

  cudaFuncSetAttribute(k3_attn, cudaFuncAttributeMaxDynamicSharedMemorySize, SMEM3);

  k1_qproj<<<128, 128>>>(clip, Wq, bq);
  k2_qk<<<128, 256>>>(Wk, temp);
  k3_attn<<<BB, 512, SMEM3>>>(dino);
  k4_out<<<BB, 1024>>>(Wv, bv, gamma, beta, out);
}

// round 17
// speedup vs baseline: 1.1567x; 1.0096x over previous
#include <cuda_runtime.h>
#include <cuda_bf16.h>

#define BB     128
#define NTOK   1369
#define DINOD  384
#define CLIPD  512
#define NH     8
#define TILE   32
#define CHUNKS 43                 // ceil(1369/32)
#define BUFF   (TILE*DINOD)       // 12288 floats per buffer

// k3 smem layout (floats)
#define OFF_LG  (2*BUFF)              // 24576 : 32*8 logits
#define OFF_WSM (OFF_LG + TILE*NH)    // 24832 : 32*8 weights
#define OFF_RS  (OFF_WSM + TILE*NH)   // 25088 : 8 rescale
#define OFF_LS  (OFF_RS + 8)          // 25096 : 8 running l
#define OFF_MB  25104                 // 2 mbarriers (16 bytes), 16B-aligned
#define SMEM3   ((OFF_MB + 4)*4)      // 100432 bytes

__device__ __align__(16) float g_Q[BB*CLIPD];
__device__ __align__(16) float g_qk[BB*NH*DINOD];
__device__ __align__(16) float g_ctx[BB*DINOD*NH];   // normalized ctx, layout [b][c][h]

// ---- packed f32x2 helpers ----
__device__ __forceinline__ unsigned long long pk2(float x, float y){
  unsigned long long r; asm("mov.b64 %0, {%1,%2};" : "=l"(r) : "f"(x), "f"(y)); return r;
}
__device__ __forceinline__ float2 upk2(unsigned long long v){
  float2 r; asm("mov.b64 {%0,%1}, %2;" : "=f"(r.x), "=f"(r.y) : "l"(v)); return r;
}
__device__ __forceinline__ void fma2(unsigned long long& d, unsigned long long a, unsigned long long b){
  asm("fma.rn.f32x2 %0, %1, %2, %0;" : "+l"(d) : "l"(a), "l"(b));
}
__device__ __forceinline__ void mul2(unsigned long long& d, unsigned long long a){
  asm("mul.rn.f32x2 %0, %0, %1;" : "+l"(d) : "l"(a));
}

// ---- mbarrier helpers ----
__device__ __forceinline__ void mbar_init(unsigned mbar, unsigned count){
  asm volatile("mbarrier.init.shared.b64 [%0], %1;" :: "r"(mbar), "r"(count) : "memory");
}
__device__ __forceinline__ void mbar_expect_tx(unsigned mbar, unsigned bytes){
  asm volatile("mbarrier.arrive.expect_tx.shared.b64 _, [%0], %1;" :: "r"(mbar), "r"(bytes) : "memory");
}
__device__ __forceinline__ void mbar_wait(unsigned mbar, unsigned parity){
  asm volatile(
    "{\n\t"
    ".reg .pred P1;\n\t"
    "WAIT_LOOP_%=:\n\t"
    "mbarrier.try_wait.parity.acquire.cta.shared::cta.b64 P1, [%0], %1, 0x989680;\n\t"
    "@P1 bra.uni WAIT_DONE_%=;\n\t"
    "bra.uni WAIT_LOOP_%=;\n\t"
    "WAIT_DONE_%=:\n\t"
    "}"
    :: "r"(mbar), "r"(parity) : "memory");
}
__device__ __forceinline__ void bulk_load(unsigned dst_smem, const void* src, unsigned bytes, unsigned mbar){
  asm volatile(
    "cp.async.bulk.shared::cta.global.mbarrier::complete_tx::bytes [%0], [%1], %2, [%3];"
    :: "r"(dst_smem), "l"(src), "r"(bytes), "r"(mbar) : "memory");
}

// ============ K1: Q = clip @ Wq + bq  (grid 128 = 64 b-pairs x 2 col-halves) ============
__global__ void __launch_bounds__(128) k1_qproj(const float* __restrict__ clip,
                                                const float* __restrict__ Wq,
                                                const float* __restrict__ bq){
  __shared__ float cs[2][CLIPD];
  int t = threadIdx.x;
  int p = blockIdx.x >> 1, half = blockIdx.x & 1;
  int b0 = 2*p, b1 = 2*p + 1;
  for(int i = t; i < CLIPD; i += 128){
    cs[0][i] = clip[(size_t)b0*CLIPD + i];
    cs[1][i] = clip[(size_t)b1*CLIPD + i];
  }
  __syncthreads();
  int col = half*256 + 2*t;
  float2 bq2 = *(const float2*)(bq + col);
  unsigned long long A0 = pk2(bq2.x, bq2.y), A1 = A0;
  #pragma unroll 8
  for(int c = 0; c < CLIPD; c++){
    float2 w = *(const float2*)(Wq + (size_t)c*CLIPD + col);
    unsigned long long wp = pk2(w.x, w.y);
    float c0 = cs[0][c], c1 = cs[1][c];
    fma2(A0, wp, pk2(c0, c0));
    fma2(A1, wp, pk2(c1, c1));
  }
  *(float2*)(g_Q + (size_t)b0*CLIPD + col) = upk2(A0);
  *(float2*)(g_Q + (size_t)b1*CLIPD + col) = upk2(A1);
}

// ============ K2: qk[b,h,c] = sum_d Wk[c,h*64+d]*Q[b,h*64+d] / (8*temp)  (grid 128) ============
__global__ void __launch_bounds__(256) k2_qk(const float* __restrict__ Wk,
                                             const float* __restrict__ temp){
  __shared__ float Qs[CLIPD];
  int t = threadIdx.x, wid = t>>5, lane = t&31;
  int b = blockIdx.x;
  for(int i = t; i < CLIPD; i += 256) Qs[i] = g_Q[(size_t)b*CLIPD + i];
  __syncthreads();
  float inv_scale = 1.0f/(8.0f*temp[0]);
  float q4x[4], q4y[4], q4z[4], q4w[4];
  #pragma unroll
  for(int k = 0; k < 4; k++){
    float4 q = *(const float4*)(Qs + lane*4 + k*128);
    q4x[k]=q.x; q4y[k]=q.y; q4z[k]=q.z; q4w[k]=q.w;
  }
  int hb = lane >> 4;
  for(int c = wid; c < DINOD; c += 8){
    const float4* wr = (const float4*)(Wk + (size_t)c*CLIPD);
    float s[4];
    #pragma unroll
    for(int k = 0; k < 4; k++){
      float4 w4 = wr[lane + k*32];
      s[k] = w4.x*q4x[k] + w4.y*q4y[k] + w4.z*q4z[k] + w4.w*q4w[k];
    }
    #pragma unroll
    for(int o = 8; o; o >>= 1){
      #pragma unroll
      for(int k = 0; k < 4; k++) s[k] += __shfl_xor_sync(0xffffffffu, s[k], o);
    }
    if((lane & 15) == 0){
      #pragma unroll
      for(int k = 0; k < 4; k++)
        g_qk[((size_t)b*NH + 2*k + hb)*DINOD + c] = s[k]*inv_scale;
    }
  }
}

// ============ K3: fused streaming single-query attention ============
// grid 128 (one b per CTA), 512 thr, 1 CTA/SM.
// Chunk loads: ONE cp.async.bulk (48KB contiguous) per chunk, mbarrier complete_tx.
// Phase A: warp = (token-row, head-half); qk held in registers.
// Phase B: thread t<384 owns column t; ctx in 4 persistent f32x2 registers.
__global__ void __launch_bounds__(512, 1) k3_attn(const float* __restrict__ dino){
  extern __shared__ float sm[];
  int t = threadIdx.x, lane = t & 31, warp = t >> 5;
  int hh = warp & 1;                 // head half
  int trow = warp >> 1;              // token rows trow + 8k
  int hl = lane & 15;
  int h0 = hh*4 + (lane >> 4)*2;     // this lane's head pair
  int b = blockIdx.x;
  const float* dino_b = dino + (size_t)b*NTOK*DINOD;

  unsigned smb = (unsigned)__cvta_generic_to_shared(sm);
  unsigned mb0 = smb + OFF_MB*4;
  unsigned mb1 = mb0 + 8;

  if(t == 0){ mbar_init(mb0, 1); mbar_init(mb1, 1); }

  // qk -> registers (2 heads x 24 floats as f32x2 pairs)
  unsigned long long q0[6][2], q1[6][2];
  {
    const float* qkb = g_qk + ((size_t)b*NH + h0)*DINOD;
    #pragma unroll
    for(int j = 0; j < 6; j++){
      float4 v = *(const float4*)(qkb + j*64 + hl*4);
      q0[j][0] = pk2(v.x,v.y); q0[j][1] = pk2(v.z,v.w);
      float4 u = *(const float4*)(qkb + DINOD + j*64 + hl*4);
      q1[j][0] = pk2(u.x,u.y); q1[j][1] = pk2(u.z,u.w);
    }
  }
  __syncthreads();    // mbarrier init visible

  // prologue: issue chunk 0
  if(t == 0){
    unsigned nb = (unsigned)((NTOK < TILE ? NTOK : TILE)*DINOD*4);
    mbar_expect_tx(mb0, nb);
    bulk_load(smb, dino_b, nb, mb0);
  }

  unsigned long long A0=0ull, A1=0ull, A2=0ull, A3=0ull;   // ctx col t, head pairs
  float m_run = -1e30f, l_run = 0.0f;                       // per-lane copy, warp<8

  for(int i = 0; i < CHUNKS; i++){
    mbar_wait((i&1) ? mb1 : mb0, (i>>1)&1);   // chunk i landed
    __syncthreads();                           // prev Phase B done -> other buffer free
    if(t == 0 && i+1 < CHUNKS){
      int tok0 = (i+1)*TILE;
      int tn = NTOK - tok0; if(tn > TILE) tn = TILE;
      unsigned nb = (unsigned)(tn*DINOD*4);
      unsigned mb = ((i+1)&1) ? mb1 : mb0;
      mbar_expect_tx(mb, nb);
      bulk_load(smb + ((i+1)&1)*(BUFF*4), dino_b + (size_t)tok0*DINOD, nb, mb);
    }

    const float* dcur = sm + (i&1)*BUFF;
    int base = i*TILE;

    // ---- Phase A: warp handles 4 tokens x 4 heads ----
    #pragma unroll
    for(int k = 0; k < 4; k++){
      int tok = trow + 8*k;
      const float4* rf = (const float4*)(dcur + tok*DINOD);
      unsigned long long s0p = 0ull, s1p = 0ull;
      #pragma unroll
      for(int j = 0; j < 6; j++){
        float4 d = rf[j*16 + hl];
        unsigned long long dA = pk2(d.x,d.y), dB = pk2(d.z,d.w);
        fma2(s0p, dA, q0[j][0]); fma2(s0p, dB, q0[j][1]);
        fma2(s1p, dA, q1[j][0]); fma2(s1p, dB, q1[j][1]);
      }
      float2 P0 = upk2(s0p), P1 = upk2(s1p);
      float s0 = P0.x + P0.y, s1 = P1.x + P1.y;
      #pragma unroll
      for(int o = 8; o; o >>= 1){
        s0 += __shfl_xor_sync(0xffffffffu, s0, o);
        s1 += __shfl_xor_sync(0xffffffffu, s1, o);
      }
      if(hl == 0){
        bool valid = (base + tok < NTOK);
        *(float2*)(sm + OFF_LG + tok*NH + h0) =
            valid ? make_float2(s0, s1) : make_float2(-1e30f, -1e30f);
      }
    }
    __syncthreads();
    // ---- softmax bookkeeping: warp h (h<8) handles head h over 32 tokens ----
    if(warp < 8){
      float lgv = sm[OFF_LG + lane*NH + warp];
      float mx = lgv;
      #pragma unroll
      for(int o = 16; o; o >>= 1) mx = fmaxf(mx, __shfl_xor_sync(0xffffffffu, mx, o));
      float mn = fmaxf(m_run, mx);
      float r  = __expf(m_run - mn);
      m_run = mn;
      float wv = __expf(lgv - mn);
      float ls = wv;
      #pragma unroll
      for(int o = 16; o; o >>= 1) ls += __shfl_xor_sync(0xffffffffu, ls, o);
      l_run = l_run*r + ls;
      sm[OFF_WSM + lane*NH + warp] = wv;
      if(lane == 0){ sm[OFF_RS + warp] = r; sm[OFF_LS + warp] = l_run; }
    }
    __syncthreads();
    // ---- Phase B: ctx update in registers (thread = column) ----
    if(t < DINOD){
      ulonglong2 ra = *(const ulonglong2*)(sm + OFF_RS);
      ulonglong2 rb = *(const ulonglong2*)(sm + OFF_RS + 4);
      mul2(A0, ra.x); mul2(A1, ra.y); mul2(A2, rb.x); mul2(A3, rb.y);
      const float* dc = dcur + t;
      #pragma unroll 4
      for(int n = 0; n < TILE; n++){
        float dv = dc[n*DINOD];
        unsigned long long dd = pk2(dv, dv);
        ulonglong2 wa = *(const ulonglong2*)(sm + OFF_WSM + n*NH);
        ulonglong2 wb = *(const ulonglong2*)(sm + OFF_WSM + n*NH + 4);
        fma2(A0, wa.x, dd); fma2(A1, wa.y, dd);
        fma2(A2, wb.x, dd); fma2(A3, wb.y, dd);
      }
    }
  }

  // normalize and store ctx
  if(t < DINOD){
    float4 l0 = *(const float4*)(sm + OFF_LS);
    float4 l1 = *(const float4*)(sm + OFF_LS + 4);
    unsigned long long i01 = pk2(1.0f/l0.x, 1.0f/l0.y);
    unsigned long long i23 = pk2(1.0f/l0.z, 1.0f/l0.w);
    unsigned long long i45 = pk2(1.0f/l1.x, 1.0f/l1.y);
    unsigned long long i67 = pk2(1.0f/l1.z, 1.0f/l1.w);
    mul2(A0, i01); mul2(A1, i23); mul2(A2, i45); mul2(A3, i67);
    float2 p0 = upk2(A0), p1 = upk2(A1), p2 = upk2(A2), p3 = upk2(A3);
    float* dst = g_ctx + ((size_t)b*DINOD + t)*NH;
    ((float4*)dst)[0] = make_float4(p0.x, p0.y, p1.x, p1.y);
    ((float4*)dst)[1] = make_float4(p2.x, p2.y, p3.x, p3.y);
  }
}

// ============ K4: out = ctx @ Wv + bv, LayerNorm  (grid 128, 1024 thr) ============
__global__ void __launch_bounds__(1024) k4_out(const float* __restrict__ Wv,
                                               const float* __restrict__ bv,
                                               const float* __restrict__ gamma,
                                               const float* __restrict__ beta,
                                               float* __restrict__ out){
  __shared__ float cs[DINOD*NH];   // ctx, layout [c][h]
  __shared__ float red2[CLIPD];
  __shared__ float redS[16], redQ[16];
  __shared__ float stats[2];
  int t = threadIdx.x;
  int b = blockIdx.x;
  for(int i = t; i < DINOD*NH; i += 1024)
    cs[i] = g_ctx[(size_t)b*DINOD*NH + i];
  __syncthreads();
  int cg = t >> 9, col = t & 511, h = col >> 6;
  float acc = cg ? 0.0f : bv[col];
  {
    int c0 = cg*192;
    const float* wp = Wv + (size_t)c0*CLIPD + col;
    const float* cp = cs + c0*NH + h;
    #pragma unroll 8
    for(int c = 0; c < 192; c++)
      acc = fmaf(cp[c*NH], wp[(size_t)c*CLIPD], acc);
  }
  if(cg) red2[col] = acc;
  __syncthreads();
  float a = 0.0f;
  if(!cg){
    a = acc + red2[col];
    float s = a, q = a*a;
    #pragma unroll
    for(int o = 16; o; o >>= 1){
      s += __shfl_xor_sync(0xffffffffu, s, o);
      q += __shfl_xor_sync(0xffffffffu, q, o);
    }
    if((t&31) == 0){ redS[t>>5] = s; redQ[t>>5] = q; }
  }
  __syncthreads();
  if(t < 32){
    float v = (t < 16) ? redS[t] : redQ[t-16];
    #pragma unroll
    for(int o = 8; o; o >>= 1) v += __shfl_xor_sync(0xffffffffu, v, o);
    if(t == 0)  stats[0] = v;
    if(t == 16) stats[1] = v;
  }
  __syncthreads();
  if(!cg){
    float mu = stats[0]*(1.0f/512.0f);
    float var = stats[1]*(1.0f/512.0f) - mu*mu;
    float rstd = rsqrtf(var + 1e-5f);
    out[(size_t)b*CLIPD + col] = (a - mu)*rstd*gamma[col] + beta[col];
  }
}

extern "C" void kernel_launch(void* const* d_in, const int* in_sizes, int n_in,
                              void* d_out, int out_size) {
  const float* dino  = (const float*)d_in[0];
  const float* clip  = (const float*)d_in[1];
  const float* Wq    = (const float*)d_in[2];
  const float* bq    = (const float*)d_in[3];
  const float* Wk    = (const float*)d_in[4];
  // d_in[5] = bk: cancels in softmax
  const float* Wv    = (const float*)d_in[6];
  const float* bv    = (const float*)d_in[7];
  const float* temp  = (const float*)d_in[8];
  const float* gamma = (const float*)d_in[9];
  const float* beta  = (const float*)d_in[10];
  float* out = (float*)d_out;

  cudaFuncSetAttribute(k3_attn, cudaFuncAttributeMaxDynamicSharedMemorySize, SMEM3);

  k1_qproj<<<128, 128>>>(clip, Wq, bq);
  k2_qk<<<128, 256>>>(Wk, temp);
  k3_attn<<<BB, 512, SMEM3>>>(dino);
  k4_out<<<BB, 1024>>>(Wv, bv, gamma, beta, out);
}